// round 1
// baseline (speedup 1.0000x reference)
#include <cuda_runtime.h>
#include <cuda_bf16.h>
#include <math.h>

// Problem constants
#define N_PROP   2048
#define N_CLS    81
#define N_FG     80
#define IMG_W    1333.0f
#define IMG_H    800.0f
#define SCORE_TH 0.05f
#define NMS_TH   0.5f
#define DETS     100
#define BBOX_CLIP 4.135166556742356f   // log(1000/16)
#define FLAT_TOT (N_FG * N_PROP)       // 163840

#define CAP3 16384                      // stage-3 sort capacity

typedef unsigned long long u64;
typedef unsigned int u32;

// ------------------- device scratch (no allocations allowed) -------------------
__device__ float  g_rowmax[N_PROP];
__device__ float  g_rowsum[N_PROP];
__device__ float4 g_prop[N_PROP];            // w, h, cx, cy per proposal
__device__ int    g_cnt;
__device__ u64    g_cand[CAP3];              // key = ord(score)<<32 | (~flat)
__device__ unsigned char g_kept[FLAT_TOT];

// ------------------- helpers -------------------
__device__ __forceinline__ u32 ord32(float f) {
    u32 u = __float_as_uint(f);
    return (u & 0x80000000u) ? ~u : (u | 0x80000000u);
}
__device__ __forceinline__ float unord32(u32 u) {
    u32 b = (u & 0x80000000u) ? (u & 0x7FFFFFFFu) : ~u;
    return __uint_as_float(b);
}

// decode + clip box for (proposal n, class cls) — matches reference math
__device__ __forceinline__ float4 decode_clip(const float* __restrict__ reg, int n, int cls) {
    float4 p = g_prop[n];  // w, h, cx, cy
    const float* r = reg + n * (N_CLS * 4) + cls * 4;
    float dx = r[0] / 10.0f;
    float dy = r[1] / 10.0f;
    float dw = fminf(r[2] / 5.0f, BBOX_CLIP);
    float dh = fminf(r[3] / 5.0f, BBOX_CLIP);
    float pcx = dx * p.x + p.z;
    float pcy = dy * p.y + p.w;
    float pw  = expf(dw) * p.x;
    float ph  = expf(dh) * p.y;
    float x1 = pcx - 0.5f * pw;
    float y1 = pcy - 0.5f * ph;
    float x2 = pcx + 0.5f * pw - 1.0f;
    float y2 = pcy + 0.5f * ph - 1.0f;
    x1 = fminf(fmaxf(x1, 0.0f), IMG_W - 1.0f);
    x2 = fminf(fmaxf(x2, 0.0f), IMG_W - 1.0f);
    y1 = fminf(fmaxf(y1, 0.0f), IMG_H - 1.0f);
    y2 = fminf(fmaxf(y2, 0.0f), IMG_H - 1.0f);
    return make_float4(x1, y1, x2, y2);
}

__device__ __forceinline__ float prob_of(const float* __restrict__ logits, int n, int c) {
    return expf(logits[n * N_CLS + c] - g_rowmax[n]) / g_rowsum[n];
}

// descending bitonic sort of keys[0..P), P power of 2, block-cooperative
__device__ __forceinline__ void bitonic_desc(u64* keys, int P, int tid, int nthr) {
    for (int k = 2; k <= P; k <<= 1) {
        for (int j = k >> 1; j > 0; j >>= 1) {
            for (int i = tid; i < P; i += nthr) {
                int ixj = i ^ j;
                if (ixj > i) {
                    u64 a = keys[i], b = keys[ixj];
                    bool desc = ((i & k) == 0);
                    if ((a < b) == desc) { keys[i] = b; keys[ixj] = a; }
                }
            }
            __syncthreads();
        }
    }
}

// ------------------- stage 1: softmax stats + proposal stats + resets -------------------
__global__ void stage1_kernel(const float* __restrict__ logits,
                              const float* __restrict__ props) {
    int t = blockIdx.x * blockDim.x + threadIdx.x;
    int nthr = gridDim.x * blockDim.x;

    for (int i = t; i < FLAT_TOT; i += nthr) g_kept[i] = 0;
    if (t == 0) g_cnt = 0;

    int row = t >> 5;
    int lane = t & 31;
    if (row < N_PROP) {
        const float* lr = logits + row * N_CLS;
        float m = -3.0e38f;
        for (int c = lane; c < N_CLS; c += 32) m = fmaxf(m, lr[c]);
        #pragma unroll
        for (int o = 16; o; o >>= 1) m = fmaxf(m, __shfl_xor_sync(0xFFFFFFFFu, m, o));
        float s = 0.0f;
        for (int c = lane; c < N_CLS; c += 32) s += expf(lr[c] - m);
        #pragma unroll
        for (int o = 16; o; o >>= 1) s += __shfl_xor_sync(0xFFFFFFFFu, s, o);
        if (lane == 0) {
            g_rowmax[row] = m;
            g_rowsum[row] = s;
            const float* p = props + row * 4;
            float w = p[2] - p[0] + 1.0f;
            float h = p[3] - p[1] + 1.0f;
            g_prop[row] = make_float4(w, h, p[0] + 0.5f * w, p[1] + 0.5f * h);
        }
    }
}

// ------------------- stage 2: per-class threshold + sort + greedy NMS -------------------
// one block per foreground class
__global__ void stage2_kernel(const float* __restrict__ logits,
                              const float* __restrict__ reg) {
    extern __shared__ char sm[];
    u64*    keys = (u64*)sm;                                   // [N_PROP]
    float4* sb   = (float4*)(sm + N_PROP * sizeof(u64));       // [N_PROP] indexed by n
    unsigned char* supp = (unsigned char*)(sm + N_PROP * sizeof(u64) + N_PROP * sizeof(float4));
    __shared__ int s_cnt;

    int tid = threadIdx.x;
    int cls = blockIdx.x + 1;  // foreground class 1..80

    if (tid == 0) s_cnt = 0;
    __syncthreads();

    // compaction: valid candidates -> (keyed by score, low bits carry proposal idx)
    for (int n = tid; n < N_PROP; n += blockDim.x) {
        float p = prob_of(logits, n, cls);
        if (p > SCORE_TH) {
            int slot = atomicAdd(&s_cnt, 1);
            keys[slot] = ((u64)ord32(p) << 32) | (u64)(0xFFFFFFFFu - (u32)n);
            sb[n] = decode_clip(reg, n, cls);
        }
    }
    __syncthreads();

    int M = s_cnt;
    if (M == 0) return;

    int P = 1;
    while (P < M) P <<= 1;
    if (P < 2) P = 2;

    for (int i = M + tid; i < P; i += blockDim.x) keys[i] = 0ULL;
    for (int i = tid; i < M; i += blockDim.x) supp[i] = 0;
    __syncthreads();

    bitonic_desc(keys, P, tid, blockDim.x);  // desc by score, asc by proposal idx on ties

    // greedy NMS over sorted valid list
    for (int i = 0; i < M; i++) {
        if (!supp[i]) {
            u32 ni = 0xFFFFFFFFu - (u32)(keys[i] & 0xFFFFFFFFu);
            float4 bi = sb[ni];
            float ai = (bi.z - bi.x + 1.0f) * (bi.w - bi.y + 1.0f);
            if (tid == 0) {
                int flat = (cls - 1) * N_PROP + (int)ni;
                int pos = atomicAdd(&g_cnt, 1);
                if (pos < CAP3)
                    g_cand[pos] = (keys[i] & 0xFFFFFFFF00000000ULL) |
                                  (u64)(0xFFFFFFFFu - (u32)flat);
                g_kept[flat] = 1;
            }
            for (int j = i + 1 + tid; j < M; j += blockDim.x) {
                if (!supp[j]) {
                    u32 nj = 0xFFFFFFFFu - (u32)(keys[j] & 0xFFFFFFFFu);
                    float4 bj = sb[nj];
                    float xx1 = fmaxf(bi.x, bj.x);
                    float yy1 = fmaxf(bi.y, bj.y);
                    float xx2 = fminf(bi.z, bj.z);
                    float yy2 = fminf(bi.w, bj.w);
                    float w = fmaxf(xx2 - xx1 + 1.0f, 0.0f);
                    float h = fmaxf(yy2 - yy1 + 1.0f, 0.0f);
                    float inter = w * h;
                    float aj = (bj.z - bj.x + 1.0f) * (bj.w - bj.y + 1.0f);
                    float iou = inter / (ai + aj - inter);
                    if (iou > NMS_TH) supp[j] = 1;
                }
            }
        }
        __syncthreads();
    }
}

// ------------------- stage 3: global top-100 + output -------------------
__global__ void stage3_kernel(const float* __restrict__ reg,
                              float* __restrict__ out) {
    extern __shared__ char sm[];
    u64* keys = (u64*)sm;   // [CAP3]
    __shared__ int s_K;

    int tid = threadIdx.x;
    int K = g_cnt;
    if (K > CAP3) K = CAP3;

    for (int i = tid; i < K; i += blockDim.x) keys[i] = g_cand[i];
    __syncthreads();

    // fallback: reference fills remaining slots with score=-1 at smallest
    // non-kept flat indices (top_k over masked array)
    if (tid == 0) {
        int kk = K;
        int f = 0;
        while (kk < DETS && f < FLAT_TOT) {
            if (!g_kept[f]) {
                keys[kk++] = ((u64)ord32(-1.0f) << 32) | (u64)(0xFFFFFFFFu - (u32)f);
            }
            f++;
        }
        s_K = kk;
    }
    __syncthreads();
    K = s_K;

    int P = 1;
    while (P < K) P <<= 1;
    if (P < 2) P = 2;
    for (int i = K + tid; i < P; i += blockDim.x) keys[i] = 0ULL;
    __syncthreads();

    bitonic_desc(keys, P, tid, blockDim.x);  // desc score, asc flat idx — top_k semantics

    if (tid < DETS) {
        u64 key = keys[tid];
        u32 flat = 0xFFFFFFFFu - (u32)(key & 0xFFFFFFFFu);
        float score = unord32((u32)(key >> 32));
        int c = (int)(flat >> 11);          // flat / 2048
        int n = (int)(flat & (N_PROP - 1)); // flat % 2048
        float4 b = decode_clip(reg, n, c + 1);
        out[tid * 4 + 0] = b.x;
        out[tid * 4 + 1] = b.y;
        out[tid * 4 + 2] = b.z;
        out[tid * 4 + 3] = b.w;
        out[DETS * 4 + tid] = score;
        out[DETS * 5 + tid] = (float)(c + 1);
    }
}

// ------------------- launch -------------------
extern "C" void kernel_launch(void* const* d_in, const int* in_sizes, int n_in,
                              void* d_out, int out_size) {
    const float* logits = (const float*)d_in[0];  // [2048, 81]
    const float* reg    = (const float*)d_in[1];  // [2048, 324]
    const float* props  = (const float*)d_in[2];  // [2048, 4]
    float* out = (float*)d_out;                   // 600 floats: boxes|scores|labels

    // stage 2: keys 16KB + boxes 32KB + supp 2KB = 50KB dyn smem
    size_t smem2 = (size_t)N_PROP * sizeof(u64) + (size_t)N_PROP * sizeof(float4) + N_PROP;
    // stage 3: 16384 * 8B = 128KB dyn smem
    size_t smem3 = (size_t)CAP3 * sizeof(u64);

    cudaFuncSetAttribute(stage2_kernel, cudaFuncAttributeMaxDynamicSharedMemorySize, (int)smem2);
    cudaFuncSetAttribute(stage3_kernel, cudaFuncAttributeMaxDynamicSharedMemorySize, (int)smem3);

    stage1_kernel<<<(N_PROP * 32 + 255) / 256, 256>>>(logits, props);
    stage2_kernel<<<N_FG, 256, smem2>>>(logits, reg);
    stage3_kernel<<<1, 1024, smem3>>>(reg, out);
}

// round 2
// speedup vs baseline: 2.7488x; 2.7488x over previous
#include <cuda_runtime.h>
#include <cuda_bf16.h>
#include <math.h>

// Problem constants
#define N_PROP   2048
#define N_CLS    81
#define N_FG     80
#define IMG_W    1333.0f
#define IMG_H    800.0f
#define SCORE_TH 0.05f
#define NMS_TH   0.5f
#define DETS     100
#define BBOX_CLIP 4.135166556742356f   // log(1000/16)
#define FLAT_TOT (N_FG * N_PROP)       // 163840

#define CAP3  16384                    // global candidate capacity (also stage-3 smem keys)
#define MAXC  2048                     // per-class candidate capacity (== N_PROP)
#define BITC  512                      // bitmask-NMS fast-path capacity
#define NW    (BITC / 64)              // 8 mask words per row

typedef unsigned long long u64;
typedef unsigned int u32;
typedef unsigned short u16;
typedef unsigned char u8;

// ------------------- device scratch -------------------
__device__ float  g_probs[N_FG * N_PROP];    // class-major probs [cls-1][n]
__device__ float4 g_prop[N_PROP];            // w, h, cx, cy per proposal
__device__ int    g_cnt;
__device__ u64    g_cand[CAP3];              // key = ord(score)<<32 | (~flat)
__device__ u8     g_kept[FLAT_TOT];

// ------------------- helpers -------------------
__device__ __forceinline__ u32 ord32(float f) {
    u32 u = __float_as_uint(f);
    return (u & 0x80000000u) ? ~u : (u | 0x80000000u);
}
__device__ __forceinline__ float unord32(u32 u) {
    u32 b = (u & 0x80000000u) ? (u & 0x7FFFFFFFu) : ~u;
    return __uint_as_float(b);
}

__device__ __forceinline__ float4 decode_clip(const float* __restrict__ reg, int n, int cls) {
    float4 p = g_prop[n];  // w, h, cx, cy
    const float* r = reg + n * (N_CLS * 4) + cls * 4;
    float dx = r[0] / 10.0f;
    float dy = r[1] / 10.0f;
    float dw = fminf(r[2] / 5.0f, BBOX_CLIP);
    float dh = fminf(r[3] / 5.0f, BBOX_CLIP);
    float pcx = dx * p.x + p.z;
    float pcy = dy * p.y + p.w;
    float pw  = expf(dw) * p.x;
    float ph  = expf(dh) * p.y;
    float x1 = pcx - 0.5f * pw;
    float y1 = pcy - 0.5f * ph;
    float x2 = pcx + 0.5f * pw - 1.0f;
    float y2 = pcy + 0.5f * ph - 1.0f;
    x1 = fminf(fmaxf(x1, 0.0f), IMG_W - 1.0f);
    x2 = fminf(fmaxf(x2, 0.0f), IMG_W - 1.0f);
    y1 = fminf(fmaxf(y1, 0.0f), IMG_H - 1.0f);
    y2 = fminf(fmaxf(y2, 0.0f), IMG_H - 1.0f);
    return make_float4(x1, y1, x2, y2);
}

// descending bitonic sort, block-cooperative
__device__ __forceinline__ void bitonic_desc(u64* keys, int P, int tid, int nthr) {
    for (int k = 2; k <= P; k <<= 1) {
        for (int j = k >> 1; j > 0; j >>= 1) {
            for (int i = tid; i < P; i += nthr) {
                int ixj = i ^ j;
                if (ixj > i) {
                    u64 a = keys[i], b = keys[ixj];
                    bool desc = ((i & k) == 0);
                    if ((a < b) == desc) { keys[i] = b; keys[ixj] = a; }
                }
            }
            __syncthreads();
        }
    }
}

// ------------------- stage 1: softmax probs (class-major) + proposal stats + resets ----
__global__ void stage1_kernel(const float* __restrict__ logits,
                              const float* __restrict__ props) {
    int t = blockIdx.x * blockDim.x + threadIdx.x;
    int nthr = gridDim.x * blockDim.x;

    // zero g_kept (int4 vectorized) and g_cnt
    int4* kz = (int4*)g_kept;
    for (int i = t; i < FLAT_TOT / 16; i += nthr) kz[i] = make_int4(0, 0, 0, 0);
    if (t == 0) g_cnt = 0;

    int row = t >> 5;
    int lane = t & 31;
    if (row < N_PROP) {
        const float* lr = logits + row * N_CLS;
        int c0 = lane, c1 = lane + 32, c2 = lane + 64;
        float l0 = lr[c0];
        float l1 = lr[c1];
        float l2 = (c2 < N_CLS) ? lr[c2] : -3.0e38f;
        float m = fmaxf(fmaxf(l0, l1), l2);
        #pragma unroll
        for (int o = 16; o; o >>= 1) m = fmaxf(m, __shfl_xor_sync(0xFFFFFFFFu, m, o));
        float e0 = expf(l0 - m);
        float e1 = expf(l1 - m);
        float e2 = (c2 < N_CLS) ? expf(l2 - m) : 0.0f;
        float s = e0 + e1 + e2;
        #pragma unroll
        for (int o = 16; o; o >>= 1) s += __shfl_xor_sync(0xFFFFFFFFu, s, o);
        // class-major prob store (skip background c=0)
        if (c0 >= 1) g_probs[(c0 - 1) * N_PROP + row] = e0 / s;
        g_probs[(c1 - 1) * N_PROP + row] = e1 / s;
        if (c2 < N_CLS) g_probs[(c2 - 1) * N_PROP + row] = e2 / s;
        if (lane == 0) {
            const float* p = props + row * 4;
            float w = p[2] - p[0] + 1.0f;
            float h = p[3] - p[1] + 1.0f;
            g_prop[row] = make_float4(w, h, p[0] + 0.5f * w, p[1] + 0.5f * h);
        }
    }
}

// ------------------- stage 2: per-class threshold + sort + bitmask NMS ----------------
// one block (256 threads) per foreground class
__global__ void stage2_kernel(const float* __restrict__ reg) {
    extern __shared__ char sm[];
    u64*    keys = (u64*)sm;                                 // [MAXC]  16KB
    float4* sbox = (float4*)(sm + MAXC * sizeof(u64));       // [MAXC]  32KB (sorted order)
    u64 (*mask)[NW] = (u64(*)[NW])(sm + MAXC * 24);          // [BITC][NW] 32KB
    u16* kept = (u16*)(sm + MAXC * 24 + BITC * NW * 8);      // [BITC]  1KB
    u8*  supp = (u8*)(sm + MAXC * 24 + BITC * NW * 8 + BITC * 2); // [MAXC] 2KB (fallback)
    __shared__ int s_cnt, s_nk, s_base;

    int tid = threadIdx.x;
    int cls = blockIdx.x + 1;  // foreground class 1..80

    if (tid == 0) s_cnt = 0;
    __syncthreads();

    // compaction from class-major probs (coalesced)
    const float* cp = g_probs + (cls - 1) * N_PROP;
    for (int n = tid; n < N_PROP; n += 256) {
        float p = cp[n];
        if (p > SCORE_TH) {
            int slot = atomicAdd(&s_cnt, 1);
            keys[slot] = ((u64)ord32(p) << 32) | (u64)(0xFFFFFFFFu - (u32)n);
        }
    }
    __syncthreads();

    int M = s_cnt;
    if (M == 0) return;

    int P = 1;
    while (P < M) P <<= 1;
    if (P < 2) P = 2;
    for (int i = M + tid; i < P; i += 256) keys[i] = 0ULL;
    __syncthreads();

    bitonic_desc(keys, P, tid, 256);  // desc by score, asc proposal idx on ties

    // decode boxes into sorted-slot order
    for (int s = tid; s < M; s += 256) {
        u32 n = 0xFFFFFFFFu - (u32)(keys[s] & 0xFFFFFFFFu);
        sbox[s] = decode_clip(reg, (int)n, cls);
    }
    __syncthreads();

    if (M <= BITC) {
        // --- bitmask NMS: row r = bits j>r with IoU>th ---
        for (int r = tid; r < M; r += 256) {
            float4 bi = sbox[r];
            float ai = (bi.z - bi.x + 1.0f) * (bi.w - bi.y + 1.0f);
            u64 w[NW];
            #pragma unroll
            for (int q = 0; q < NW; q++) w[q] = 0ULL;
            for (int j = r + 1; j < M; j++) {
                float4 bj = sbox[j];
                float xx1 = fmaxf(bi.x, bj.x);
                float yy1 = fmaxf(bi.y, bj.y);
                float xx2 = fminf(bi.z, bj.z);
                float yy2 = fminf(bi.w, bj.w);
                float iw = fmaxf(xx2 - xx1 + 1.0f, 0.0f);
                float ih = fmaxf(yy2 - yy1 + 1.0f, 0.0f);
                float inter = iw * ih;
                float aj = (bj.z - bj.x + 1.0f) * (bj.w - bj.y + 1.0f);
                if (inter / (ai + aj - inter) > NMS_TH)
                    w[j >> 6] |= 1ULL << (j & 63);
            }
            #pragma unroll
            for (int q = 0; q < NW; q++) mask[r][q] = w[q];
        }
        __syncthreads();

        // serial greedy scan (trivial: ~M iterations of mask ORs)
        if (tid == 0) {
            u64 rem[NW];
            #pragma unroll
            for (int q = 0; q < NW; q++) rem[q] = 0ULL;
            int nk = 0;
            for (int i = 0; i < M; i++) {
                if (!((rem[i >> 6] >> (i & 63)) & 1ULL)) {
                    kept[nk++] = (u16)i;
                    for (int q = i >> 6; q < NW; q++) rem[q] |= mask[i][q];
                }
            }
            s_nk = nk;
            s_base = atomicAdd(&g_cnt, nk);
        }
        __syncthreads();

        int nk = s_nk, base = s_base;
        for (int t = tid; t < nk; t += 256) {
            int i = kept[t];
            u64 key = keys[i];
            u32 n = 0xFFFFFFFFu - (u32)(key & 0xFFFFFFFFu);
            u32 flat = (u32)(cls - 1) * N_PROP + n;
            if (base + t < CAP3)
                g_cand[base + t] = (key & 0xFFFFFFFF00000000ULL) |
                                   (u64)(0xFFFFFFFFu - flat);
            g_kept[flat] = 1;
        }
    } else {
        // --- fallback: serial greedy NMS (M > BITC; never triggers on this input) ---
        for (int i = tid; i < M; i += 256) supp[i] = 0;
        __syncthreads();
        for (int i = 0; i < M; i++) {
            if (!supp[i]) {
                float4 bi = sbox[i];
                float ai = (bi.z - bi.x + 1.0f) * (bi.w - bi.y + 1.0f);
                if (tid == 0) {
                    u32 n = 0xFFFFFFFFu - (u32)(keys[i] & 0xFFFFFFFFu);
                    u32 flat = (u32)(cls - 1) * N_PROP + n;
                    int pos = atomicAdd(&g_cnt, 1);
                    if (pos < CAP3)
                        g_cand[pos] = (keys[i] & 0xFFFFFFFF00000000ULL) |
                                      (u64)(0xFFFFFFFFu - flat);
                    g_kept[flat] = 1;
                }
                for (int j = i + 1 + tid; j < M; j += 256) {
                    if (!supp[j]) {
                        float4 bj = sbox[j];
                        float xx1 = fmaxf(bi.x, bj.x);
                        float yy1 = fmaxf(bi.y, bj.y);
                        float xx2 = fminf(bi.z, bj.z);
                        float yy2 = fminf(bi.w, bj.w);
                        float iw = fmaxf(xx2 - xx1 + 1.0f, 0.0f);
                        float ih = fmaxf(yy2 - yy1 + 1.0f, 0.0f);
                        float inter = iw * ih;
                        float aj = (bj.z - bj.x + 1.0f) * (bj.w - bj.y + 1.0f);
                        if (inter / (ai + aj - inter) > NMS_TH) supp[j] = 1;
                    }
                }
            }
            __syncthreads();
        }
    }
}

// ------------------- stage 3: exact radix-select top-100 + output --------------------
__global__ void stage3_kernel(const float* __restrict__ reg,
                              float* __restrict__ out) {
    extern __shared__ u64 keys[];   // [CAP3] 128KB
    __shared__ u32 hist[256];
    __shared__ u64 s_prefix, s_T;
    __shared__ int s_r, s_cnt, s_K, s_selcnt;
    __shared__ u64 sel[DETS];

    int tid = threadIdx.x;
    const int nthr = 1024;

    int K = g_cnt;
    if (K > CAP3) K = CAP3;
    for (int i = tid; i < K; i += nthr) keys[i] = g_cand[i];
    if (tid == 0) { s_prefix = 0ULL; s_r = DETS; s_selcnt = 0; s_cnt = 0; }
    __syncthreads();

    // fallback fill to reach >= DETS candidates (reference's -1-masked top_k behavior)
    if (tid == 0) {
        int kk = K;
        int f = 0;
        while (kk < DETS && f < FLAT_TOT) {
            if (!g_kept[f])
                keys[kk++] = ((u64)ord32(-1.0f) << 32) | (u64)(0xFFFFFFFFu - (u32)f);
            f++;
        }
        s_K = kk;
    }
    __syncthreads();
    K = s_K;

    // MSB-first 8-bit radix select of the exact 100th-largest 64-bit key
    bool done = false;
    for (int shift = 56; shift >= 0 && !done; shift -= 8) {
        if (tid < 256) hist[tid] = 0;
        __syncthreads();
        u64 hm  = (shift == 56) ? 0ULL : (~0ULL) << (shift + 8);
        u64 pfx = s_prefix;
        // warp-aggregated histogram (top byte has only ~3 distinct values)
        for (int base = 0; base < K; base += nthr) {
            int i = base + tid;
            bool v = (i < K);
            u64 k = v ? keys[i] : 0ULL;
            bool mt = v && ((k & hm) == pfx);
            u32 b = mt ? (u32)((k >> shift) & 255u) : 0xFFFFFFFFu;
            u32 grp = __match_any_sync(0xFFFFFFFFu, b);
            if (mt && ((__ffs(grp) - 1) == (tid & 31)))
                atomicAdd(&hist[b], __popc(grp));
        }
        __syncthreads();
        if (tid < 32) {
            int r0 = s_r;
            __syncwarp();
            u32 h[8]; u32 cs = 0;
            #pragma unroll
            for (int q = 0; q < 8; q++) { h[q] = hist[tid * 8 + q]; cs += h[q]; }
            u32 p = cs;
            #pragma unroll
            for (int o = 1; o < 32; o <<= 1) {
                u32 vv = __shfl_up_sync(0xFFFFFFFFu, p, o);
                if (tid >= o) p += vv;
            }
            u32 total = __shfl_sync(0xFFFFFFFFu, p, 31);
            u32 run = total - p;   // count of keys in higher bins (higher lanes = higher bins)
            int chosen = -1; u32 newr = 0, cinb = 0;
            for (int q = 7; q >= 0; q--) {
                if (chosen < 0 && run < (u32)r0 && (u32)r0 <= run + h[q]) {
                    chosen = tid * 8 + q; newr = (u32)r0 - run; cinb = h[q];
                }
                run += h[q];
            }
            if (chosen >= 0) {
                s_prefix = pfx | ((u64)(u32)chosen << shift);
                s_r = (int)newr;
                s_cnt = (int)cinb;
            }
        }
        __syncthreads();
        if (s_cnt == 1) {
            // unique match: its full key is the exact 100th-largest
            u64 hm2 = (shift == 0) ? ~0ULL : (~0ULL) << shift;
            u64 pfx2 = s_prefix;
            for (int i = tid; i < K; i += nthr) {
                u64 k = keys[i];
                if ((k & hm2) == pfx2) s_T = k;
            }
            done = true;
        }
        __syncthreads();
    }
    u64 T = s_T;

    // select exactly the 100 keys >= T (keys are unique)
    for (int i = tid; i < K; i += nthr) {
        u64 k = keys[i];
        if (k >= T) {
            int s = atomicAdd(&s_selcnt, 1);
            if (s < DETS) sel[s] = k;
        }
    }
    __syncthreads();

    if (tid < DETS) {
        u64 my = sel[tid];
        int rank = 0;
        for (int q = 0; q < DETS; q++) rank += (sel[q] > my);
        u32 flat = 0xFFFFFFFFu - (u32)(my & 0xFFFFFFFFu);
        float score = unord32((u32)(my >> 32));
        int c = (int)(flat >> 11);           // flat / 2048
        int n = (int)(flat & (N_PROP - 1));  // flat % 2048
        float4 b = decode_clip(reg, n, c + 1);
        out[rank * 4 + 0] = b.x;
        out[rank * 4 + 1] = b.y;
        out[rank * 4 + 2] = b.z;
        out[rank * 4 + 3] = b.w;
        out[DETS * 4 + rank] = score;
        out[DETS * 5 + rank] = (float)(c + 1);
    }
}

// ------------------- launch -------------------
extern "C" void kernel_launch(void* const* d_in, const int* in_sizes, int n_in,
                              void* d_out, int out_size) {
    const float* logits = (const float*)d_in[0];  // [2048, 81]
    const float* reg    = (const float*)d_in[1];  // [2048, 324]
    const float* props  = (const float*)d_in[2];  // [2048, 4]
    float* out = (float*)d_out;                   // 600 floats: boxes|scores|labels

    size_t smem2 = (size_t)MAXC * 24 + (size_t)BITC * NW * 8 + (size_t)BITC * 2 + MAXC; // ~85KB
    size_t smem3 = (size_t)CAP3 * sizeof(u64);                                          // 128KB

    cudaFuncSetAttribute(stage2_kernel, cudaFuncAttributeMaxDynamicSharedMemorySize, (int)smem2);
    cudaFuncSetAttribute(stage3_kernel, cudaFuncAttributeMaxDynamicSharedMemorySize, (int)smem3);

    stage1_kernel<<<(N_PROP * 32 + 255) / 256, 256>>>(logits, props);
    stage2_kernel<<<N_FG, 256, smem2>>>(reg);
    stage3_kernel<<<1, 1024, smem3>>>(reg, out);
}